// round 6
// baseline (speedup 1.0000x reference)
#include <cuda_runtime.h>
#include <cstdint>
#include <cstddef>

#define BATCH 1024
#define LSEQ  512
#define DIM   64
#define KCAP  8
#define NEGV  (-65535.0f)
#define NTHREADS 512
#define LHALF 256      // rows of X per CTA (cluster of 2 splits L)
#define XSS 68         // X row stride in floats (272B = 17*16: cp.async-aligned, conflict-free)
#define SSS 67
#define CPS 10

// ---- shared memory layout (float offsets) ----
#define WT_OFF     0                        // W^T local [256][8]       2048
#define XS_OFF     2048                     // X local [256][68]        17408
#define SS_OFF     19456                    // S [64][67]               4288
#define CPART_OFF  23744                    // pass1 partials [4][64][10] 2560
#define CPL_OFF    26304                    // C' local half [512]
#define CPF_OFF    26816                    // C' full [512]
#define CS_OFF     27328                    // Cs / high [512]
#define SCALE_OFF  27840                    // squash scale [64]
#define HST_OFF    27904                    // hs^T [64][8]             512
#define SMEM_FLOATS 28416
#define SMEM_BYTES  (SMEM_FLOATS * 4)       // 113664 B -> 2 CTAs/SM

__device__ float g_B[KCAP * LSEQ];
__device__ float g_scratch[BATCH * KCAP * LSEQ];   // per-batch deltas (16MB)
__device__ float g_part[64 * KCAP * LSEQ];         // stage-1 reduction partials

__device__ __forceinline__ void cp_async16(uint32_t sa, const void* ga) {
    asm volatile("cp.async.cg.shared.global [%0], [%1], 16;" :: "r"(sa), "l"(ga));
}
__device__ __forceinline__ void cp_commit() {
    asm volatile("cp.async.commit_group;" ::: "memory");
}
template<int N>
__device__ __forceinline__ void cp_wait() {
    asm volatile("cp.async.wait_group %0;" :: "n"(N) : "memory");
}
__device__ __forceinline__ unsigned long long pack2(float v) {
    unsigned long long r;
    asm("mov.b64 %0, {%1, %1};" : "=l"(r) : "r"(__float_as_uint(v)));
    return r;
}
__device__ __forceinline__ void fma2(unsigned long long& acc,
                                     unsigned long long a, unsigned long long b) {
    asm("fma.rn.f32x2 %0, %1, %2, %0;" : "+l"(acc) : "l"(a), "l"(b));
}
__device__ __forceinline__ unsigned long long add2(unsigned long long a,
                                                   unsigned long long b) {
    unsigned long long r;
    asm("add.rn.f32x2 %0, %1, %2;" : "=l"(r) : "l"(a), "l"(b));
    return r;
}
__device__ __forceinline__ uint32_t ctarank() {
    uint32_t r; asm("mov.u32 %0, %%cluster_ctarank;" : "=r"(r)); return r;
}
__device__ __forceinline__ float ld_dsmem_peer(uint32_t local_addr, uint32_t peer) {
    uint32_t ra; float v;
    asm("mapa.shared::cluster.u32 %0, %1, %2;" : "=r"(ra) : "r"(local_addr), "r"(peer));
    asm volatile("ld.shared::cluster.f32 %0, [%1];" : "=f"(v) : "r"(ra));
    return v;
}
#define CLUSTER_SYNC() do { \
    asm volatile("barrier.cluster.arrive.aligned;" ::: "memory"); \
    asm volatile("barrier.cluster.wait.aligned;"   ::: "memory"); \
} while (0)

// One routing iteration. Cluster of 2 CTAs handles one batch (L split 256/256).
template<int LAST>
__global__ void __launch_bounds__(NTHREADS, 2) __cluster_dims__(2, 1, 1)
route_kernel(const float* __restrict__ X, const float* __restrict__ Sg,
             const int* __restrict__ seqlen, float* __restrict__ out)
{
    extern __shared__ float sm[];
    const int tid  = threadIdx.x;
    const int w    = tid >> 5;            // 16 warps
    const int lane = tid & 31;
    const uint32_t rank = ctarank();
    const int b    = blockIdx.x >> 1;
    const float* Xg = X + ((size_t)b * LSEQ + rank * LHALF) * DIM;
    const int slen = seqlen[b];

    // ---- warp-owned X staging: warp w owns local rows [16w,16w+16), 2 groups of 8 ----
    const uint32_t xs_base = (uint32_t)__cvta_generic_to_shared(&sm[XS_OFF]);
    const int row0 = w * 16;
    #pragma unroll
    for (int g2 = 0; g2 < 2; g2++) {
        #pragma unroll
        for (int h = 0; h < 4; h++) {
            int s   = lane + 32 * h;               // 0..127
            int r8  = s >> 4;
            int col = s & 15;
            int row = row0 + 8 * g2 + r8;
            cp_async16(xs_base + (uint32_t)(row * (XSS * 4) + col * 16),
                       (const void*)(Xg + row * DIM + col * 4));
        }
        cp_commit();
    }

    // stage S [64][67] (512 thr x 2 float4)
    #pragma unroll
    for (int i = 0; i < 2; i++) {
        int j = tid + i * 512;
        int d = j >> 4, o4 = (j & 15) * 4;
        float4 v = *(const float4*)(Sg + j * 4);
        float* p = &sm[SS_OFF + d * SSS + o4];
        p[0] = v.x; p[1] = v.y; p[2] = v.z; p[3] = v.w;
    }

    // masked softmax over full L (redundant per CTA); store only local W^T rows
    if (w < 8) {
        const int k = w;
        float v[16];
        #pragma unroll
        for (int j = 0; j < 16; j++) {
            int l = lane + 32 * j;
            float bv = g_B[k * LSEQ + l];
            v[j] = (l < slen) ? bv : NEGV;
        }
        float m = v[0];
        #pragma unroll
        for (int j = 1; j < 16; j++) m = fmaxf(m, v[j]);
        #pragma unroll
        for (int off = 16; off > 0; off >>= 1)
            m = fmaxf(m, __shfl_xor_sync(0xffffffffu, m, off));
        float s = 0.f;
        #pragma unroll
        for (int j = 0; j < 16; j++) { v[j] = __expf(v[j] - m); s += v[j]; }
        #pragma unroll
        for (int off = 16; off > 0; off >>= 1)
            s += __shfl_xor_sync(0xffffffffu, s, off);
        float inv = 1.0f / s;
        #pragma unroll
        for (int j = 0; j < 16; j++) {
            int l = lane + 32 * j;
            if ((uint32_t)(l >> 8) == rank)
                sm[WT_OFF + (l - (int)rank * LHALF) * 8 + k] = v[j] * inv;
        }
    }
    __syncthreads();   // W^T(local) + S visible

    // ---- pass 1 (local half): C'h[k][d] = sum_{l local} W[k][l]*X[l][d] ----
    unsigned long long acc2[8];
    #pragma unroll
    for (int i = 0; i < 8; i++) acc2[i] = 0ull;

    #pragma unroll
    for (int g2 = 0; g2 < 2; g2++) {
        if (g2 == 0) cp_wait<1>(); else cp_wait<0>();
        __syncwarp();
        #pragma unroll
        for (int r = 0; r < 8; r++) {
            int l = row0 + 8 * g2 + r;
            float2 xv = *(const float2*)&sm[XS_OFF + l * XSS + 2 * lane];
            ulonglong2 wA = *(const ulonglong2*)&sm[WT_OFF + l * 8];
            ulonglong2 wB = *(const ulonglong2*)&sm[WT_OFF + l * 8 + 4];
            unsigned long long xx0 = pack2(xv.x);
            unsigned long long xx1 = pack2(xv.y);
            fma2(acc2[0], xx0, wA.x); fma2(acc2[1], xx0, wA.y);
            fma2(acc2[2], xx0, wB.x); fma2(acc2[3], xx0, wB.y);
            fma2(acc2[4], xx1, wA.x); fma2(acc2[5], xx1, wA.y);
            fma2(acc2[6], xx1, wB.x); fma2(acc2[7], xx1, wB.y);
        }
    }

    // staged cross-warp reduction into 4 buffers [64][10]
    {
        int buf = w & 3;
        if (w < 4) {
            #pragma unroll
            for (int dd = 0; dd < 2; dd++)
                #pragma unroll
                for (int kp = 0; kp < 4; kp++) {
                    int d = 2 * lane + dd;
                    *(unsigned long long*)&sm[CPART_OFF + buf * 640 + d * CPS + 2 * kp]
                        = acc2[dd * 4 + kp];
                }
        }
        __syncthreads();
        #pragma unroll
        for (int stage = 1; stage < 4; stage++) {
            if ((w >> 2) == stage) {
                #pragma unroll
                for (int dd = 0; dd < 2; dd++)
                    #pragma unroll
                    for (int kp = 0; kp < 4; kp++) {
                        int d = 2 * lane + dd;
                        unsigned long long* p =
                            (unsigned long long*)&sm[CPART_OFF + buf * 640 + d * CPS + 2 * kp];
                        *p = add2(*p, acc2[dd * 4 + kp]);
                    }
            }
            __syncthreads();
        }
    }
    {   // final 4-way sum -> local C' half
        int k = tid >> 6, d = tid & 63;
        float s = 0.f;
        #pragma unroll
        for (int p = 0; p < 4; p++) s += sm[CPART_OFF + p * 640 + d * CPS + k];
        sm[CPL_OFF + tid] = s;
    }

    // ---- cross-CTA combine via DSMEM ----
    CLUSTER_SYNC();    // release local CPL writes / acquire peer's
    {
        uint32_t my = (uint32_t)__cvta_generic_to_shared(&sm[CPL_OFF + tid]);
        float pv = ld_dsmem_peer(my, rank ^ 1u);
        sm[CPF_OFF + tid] = pv + sm[CPL_OFF + tid];
    }
    CLUSTER_SYNC();    // peers done reading CPL; also block-syncs CPF

    // ---- Cs[k][o] = sum_d C'[k][d]*S[d][o] (redundant in both CTAs) ----
    {
        int k = tid >> 6, o = tid & 63;
        float a = 0.f;
        #pragma unroll
        for (int d = 0; d < 64; d++)
            a += sm[CPF_OFF + k * 64 + d] * sm[SS_OFF + d * SSS + o];
        sm[CS_OFF + tid] = a;
    }
    __syncthreads();

    // ---- squash over capsule dim ----
    if (tid < 64) {
        float sq = 0.f;
        #pragma unroll
        for (int k = 0; k < 8; k++) {
            float cv = sm[CS_OFF + k * 64 + tid];
            sq += cv * cv;
        }
        sm[SCALE_OFF + tid] = (sq / (1.0f + sq)) * rsqrtf(sq + 1e-9f);
    }
    __syncthreads();

    if (LAST) {
        // each rank writes its half of the identical high vector
        if (tid < 256) {
            int e = (int)rank * 256 + tid;
            out[(size_t)b * 512 + e] = sm[SCALE_OFF + (e & 63)] * sm[CS_OFF + e];
        }
        return;
    }
    {
        float hv = sm[SCALE_OFF + (tid & 63)] * sm[CS_OFF + tid];
        sm[CS_OFF + tid] = hv;            // high, in place
    }
    __syncthreads();

    // ---- hs[k][i] = sum_o high[k][o]*S[i][o] -> hs^T[i][k] (redundant) ----
    {
        int k = tid >> 6, i = tid & 63;
        float h = 0.f;
        #pragma unroll
        for (int o = 0; o < 64; o++)
            h += sm[CS_OFF + k * 64 + o] * sm[SS_OFF + i * SSS + o];
        sm[HST_OFF + i * 8 + k] = h;
    }
    __syncthreads();

    // ---- pass 2 (local rows): delta[k][l] = sum_i hs[k][i]*X[l][i] ----
    {
        int row = tid >> 1, ks = tid & 1;          // local row, capsule group
        unsigned long long dacc2[2] = {0ull, 0ull};
        #pragma unroll
        for (int q = 0; q < 16; q++) {
            float4 x = *(const float4*)&sm[XS_OFF + row * XSS + q * 4];
            #pragma unroll
            for (int r = 0; r < 4; r++) {
                float xvf = (r == 0) ? x.x : (r == 1) ? x.y : (r == 2) ? x.z : x.w;
                unsigned long long xx = pack2(xvf);
                ulonglong2 hA = *(const ulonglong2*)&sm[HST_OFF + (q * 4 + r) * 8 + 4 * ks];
                fma2(dacc2[0], xx, hA.x);
                fma2(dacc2[1], xx, hA.y);
            }
        }
        int lg = (int)rank * LHALF + row;          // global l
        float* sc = &g_scratch[(size_t)b * 4096 + lg];
        unsigned int u0, u1, u2, u3;
        asm("mov.b64 {%0, %1}, %2;" : "=r"(u0), "=r"(u1) : "l"(dacc2[0]));
        asm("mov.b64 {%0, %1}, %2;" : "=r"(u2), "=r"(u3) : "l"(dacc2[1]));
        sc[(4 * ks + 0) * 512] = __uint_as_float(u0);
        sc[(4 * ks + 1) * 512] = __uint_as_float(u1);
        sc[(4 * ks + 2) * 512] = __uint_as_float(u2);
        sc[(4 * ks + 3) * 512] = __uint_as_float(u3);
    }
}

// Deterministic 2-stage cross-batch reduction of deltas into g_B
__global__ void reduce1_kernel() {
    int j = blockIdx.x * 256 + threadIdx.x;      // 0..4095
    int base = blockIdx.y * 16;
    float s = 0.f;
    #pragma unroll
    for (int i = 0; i < 16; i++) s += g_scratch[(size_t)(base + i) * 4096 + j];
    g_part[(size_t)blockIdx.y * 4096 + j] = s;
}
__global__ void reduce2_kernel() {
    int j = blockIdx.x * 256 + threadIdx.x;
    float s = 0.f;
    #pragma unroll
    for (int i = 0; i < 64; i++) s += g_part[(size_t)i * 4096 + j];
    g_B[j] += s;
}

extern "C" void kernel_launch(void* const* d_in, const int* in_sizes, int n_in,
                              void* d_out, int out_size)
{
    const float* X     = (const float*)d_in[0];  // low_capsule [1024,512,64]
    const float* Binit = (const float*)d_in[1];  // B_init [1,8,512]
    const float* S     = (const float*)d_in[2];  // S [64,64]
    const int*   seq   = (const int*)d_in[3];    // seq_len [1024,1]
    float* out = (float*)d_out;

    cudaFuncSetAttribute(route_kernel<0>, cudaFuncAttributeMaxDynamicSharedMemorySize, SMEM_BYTES);
    cudaFuncSetAttribute(route_kernel<1>, cudaFuncAttributeMaxDynamicSharedMemorySize, SMEM_BYTES);

    void* bptr = nullptr;
    cudaGetSymbolAddress(&bptr, g_B);
    cudaMemcpyAsync(bptr, Binit, KCAP * LSEQ * sizeof(float),
                    cudaMemcpyDeviceToDevice, 0);

    // iter 0
    route_kernel<0><<<2 * BATCH, NTHREADS, SMEM_BYTES>>>(X, S, seq, out);
    reduce1_kernel<<<dim3(16, 64), 256>>>();
    reduce2_kernel<<<16, 256>>>();
    // iter 1
    route_kernel<0><<<2 * BATCH, NTHREADS, SMEM_BYTES>>>(X, S, seq, out);
    reduce1_kernel<<<dim3(16, 64), 256>>>();
    reduce2_kernel<<<16, 256>>>();
    // iter 2 (final): writes high
    route_kernel<1><<<2 * BATCH, NTHREADS, SMEM_BYTES>>>(X, S, seq, out);
}

// round 7
// speedup vs baseline: 1.2077x; 1.2077x over previous
#include <cuda_runtime.h>
#include <cstdint>
#include <cstddef>

#define BATCH 1024
#define LSEQ  512
#define DIM   64
#define KCAP  8
#define NEGV  (-65535.0f)
#define NTHREADS 1024
#define GRID  148      // persistent: 1 CTA/SM, each loops over batches b += GRID
#define XSS 68         // X row stride (floats): conflict-free LDS.64 pass1 / LDS.128 pass2
#define SSS 67
#define CPS 10

// ---- shared memory layout (float offsets) ----
#define WT_OFF     0                        // W^T [512][8]              4096
#define XS_OFF     4096                     // X [512][68]               34816
#define SS_OFF     38912                    // S [64][67]                4288
#define CPART_OFF  43200                    // pass1 partials [16][64][10] 10240
#define CP_OFF     53440                    // C' [8][64]                512
#define P2_OFF     53952                    // 2-way partials [2][512]   1024
#define CS_OFF     54976                    // Cs / high [8][64]         512
#define SCALE_OFF  55488                    // squash scale [64]         64
#define HST_OFF    55552                    // hs^T [64][8]              512
#define SMEM_FLOATS 56064
#define SMEM_BYTES  (SMEM_FLOATS * 4)       // 224256 B (1 CTA/SM)

__device__ float g_B[KCAP * LSEQ];
__device__ float g_scratch[BATCH * KCAP * LSEQ];   // per-batch deltas (16MB)
__device__ float g_part[64 * KCAP * LSEQ];         // stage-1 reduction partials

__device__ __forceinline__ void cp_async16(uint32_t sa, const void* ga) {
    asm volatile("cp.async.cg.shared.global [%0], [%1], 16;" :: "r"(sa), "l"(ga));
}
__device__ __forceinline__ void cp_commit() {
    asm volatile("cp.async.commit_group;" ::: "memory");
}
template<int N>
__device__ __forceinline__ void cp_wait() {
    asm volatile("cp.async.wait_group %0;" :: "n"(N) : "memory");
}
__device__ __forceinline__ unsigned long long pack2(float v) {
    unsigned long long r;
    asm("mov.b64 %0, {%1, %1};" : "=l"(r) : "r"(__float_as_uint(v)));
    return r;
}
__device__ __forceinline__ void fma2(unsigned long long& acc,
                                     unsigned long long a, unsigned long long b) {
    asm("fma.rn.f32x2 %0, %1, %2, %0;" : "+l"(acc) : "l"(a), "l"(b));
}
__device__ __forceinline__ unsigned long long add2(unsigned long long a,
                                                   unsigned long long b) {
    unsigned long long r;
    asm("add.rn.f32x2 %0, %1, %2;" : "=l"(r) : "l"(a), "l"(b));
    return r;
}

// Issue this warp's 16 X rows (2 cp.async commit groups of 8 rows each).
__device__ __forceinline__ void issue_rows(const float* __restrict__ X, int b,
                                           uint32_t xs_base, int row0, int lane) {
    const float* Xg = X + (size_t)b * (LSEQ * DIM);
    #pragma unroll
    for (int g2 = 0; g2 < 2; g2++) {
        #pragma unroll
        for (int h = 0; h < 4; h++) {
            int s   = lane + 32 * h;               // 0..127
            int r8  = s >> 4;
            int col = s & 15;
            int row = row0 + 8 * g2 + r8;
            cp_async16(xs_base + (uint32_t)(row * (XSS * 4) + col * 16),
                       (const void*)(Xg + row * DIM + col * 4));
        }
        cp_commit();
    }
}

// Masked softmax for batch b (warps 0..7 only; warp k = capsule row k).
__device__ __forceinline__ void do_softmax(float* sm, const int* __restrict__ seqlen,
                                           int b, int w, int lane) {
    if (w >= 8) return;
    const int k = w;
    const int slen = seqlen[b];
    float v[16];
    #pragma unroll
    for (int j = 0; j < 16; j++) {
        int l = lane + 32 * j;
        float bv = g_B[k * LSEQ + l];
        v[j] = (l < slen) ? bv : NEGV;
    }
    float m = v[0];
    #pragma unroll
    for (int j = 1; j < 16; j++) m = fmaxf(m, v[j]);
    #pragma unroll
    for (int off = 16; off > 0; off >>= 1)
        m = fmaxf(m, __shfl_xor_sync(0xffffffffu, m, off));
    float s = 0.f;
    #pragma unroll
    for (int j = 0; j < 16; j++) { v[j] = __expf(v[j] - m); s += v[j]; }
    #pragma unroll
    for (int off = 16; off > 0; off >>= 1)
        s += __shfl_xor_sync(0xffffffffu, s, off);
    float inv = 1.0f / s;
    #pragma unroll
    for (int j = 0; j < 16; j++)
        sm[WT_OFF + (lane + 32 * j) * 8 + k] = v[j] * inv;   // W^T[l][k]
}

// Persistent kernel: one routing iteration; each CTA loops over batches b += GRID,
// prefetching batch b+GRID's X (warp-owned rows) while finishing batch b.
template<int LAST>
__global__ void __launch_bounds__(NTHREADS, 1)
route_kernel(const float* __restrict__ X, const float* __restrict__ Sg,
             const int* __restrict__ seqlen, float* __restrict__ out)
{
    extern __shared__ float sm[];
    const int tid  = threadIdx.x;
    const int w    = tid >> 5;            // 32 warps
    const int lane = tid & 31;
    const uint32_t xs_base = (uint32_t)__cvta_generic_to_shared(&sm[XS_OFF]);
    const int row0 = w * 16;              // this warp's X rows [row0, row0+16)

    int b = blockIdx.x;

    // prologue: first batch's X + S staging + first softmax
    issue_rows(X, b, xs_base, row0, lane);
    {
        int j = tid;                      // 1024 float4s = S [64][64]
        int d = j >> 4, o4 = (j & 15) * 4;
        float4 v = *(const float4*)(Sg + j * 4);
        float* p = &sm[SS_OFF + d * SSS + o4];
        p[0] = v.x; p[1] = v.y; p[2] = v.z; p[3] = v.w;
    }
    do_softmax(sm, seqlen, b, w, lane);
    __syncthreads();

    for (; b < BATCH; b += GRID) {
        const int bn = b + GRID;

        // ---- pass 1: C'[k][d] = sum_l W[k][l]*X[l][d]; warp-private rows ----
        unsigned long long acc2[8];
        #pragma unroll
        for (int i = 0; i < 8; i++) acc2[i] = 0ull;

        #pragma unroll
        for (int g2 = 0; g2 < 2; g2++) {
            if (g2 == 0) cp_wait<1>(); else cp_wait<0>();
            __syncwarp();
            #pragma unroll
            for (int r = 0; r < 8; r++) {
                int l = row0 + 8 * g2 + r;
                float2 xv = *(const float2*)&sm[XS_OFF + l * XSS + 2 * lane];
                ulonglong2 wA = *(const ulonglong2*)&sm[WT_OFF + l * 8];
                ulonglong2 wB = *(const ulonglong2*)&sm[WT_OFF + l * 8 + 4];
                unsigned long long xx0 = pack2(xv.x);
                unsigned long long xx1 = pack2(xv.y);
                fma2(acc2[0], xx0, wA.x); fma2(acc2[1], xx0, wA.y);
                fma2(acc2[2], xx0, wB.x); fma2(acc2[3], xx0, wB.y);
                fma2(acc2[4], xx1, wA.x); fma2(acc2[5], xx1, wA.y);
                fma2(acc2[6], xx1, wB.x); fma2(acc2[7], xx1, wB.y);
            }
        }

        // LAST: X dead after pass1 -> prefetch next batch's rows immediately
        if (LAST && bn < BATCH) issue_rows(X, bn, xs_base, row0, lane);

        // ---- two-wave cross-warp reduction into CPART [16][64][10] ----
        if (w < 16) {
            #pragma unroll
            for (int dd = 0; dd < 2; dd++)
                #pragma unroll
                for (int kp = 0; kp < 4; kp++) {
                    int d = 2 * lane + dd;
                    *(unsigned long long*)&sm[CPART_OFF + w * 640 + d * CPS + 2 * kp]
                        = acc2[dd * 4 + kp];
                }
        }
        __syncthreads();
        if (w >= 16) {
            int p = w - 16;
            #pragma unroll
            for (int dd = 0; dd < 2; dd++)
                #pragma unroll
                for (int kp = 0; kp < 4; kp++) {
                    int d = 2 * lane + dd;
                    unsigned long long* ptr =
                        (unsigned long long*)&sm[CPART_OFF + p * 640 + d * CPS + 2 * kp];
                    *ptr = add2(*ptr, acc2[dd * 4 + kp]);
                }
        }
        __syncthreads();
        if (tid < 512) {
            int k = tid >> 6, d = tid & 63;
            float s = 0.f;
            #pragma unroll
            for (int p = 0; p < 16; p++) s += sm[CPART_OFF + p * 640 + d * CPS + k];
            sm[CP_OFF + k * 64 + d] = s;
        }
        __syncthreads();

        // ---- Cs[k][o] = sum_d C'[k][d]*S[d][o], split over d-halves ----
        {
            int k = tid >> 7, idx = tid & 127;
            int o = idx & 63, dh = idx >> 6;
            float a = 0.f;
            #pragma unroll
            for (int dd = 0; dd < 32; dd++) {
                int d = dh * 32 + dd;
                a += sm[CP_OFF + k * 64 + d] * sm[SS_OFF + d * SSS + o];
            }
            sm[P2_OFF + dh * 512 + k * 64 + o] = a;
        }
        __syncthreads();
        if (tid < 512) sm[CS_OFF + tid] = sm[P2_OFF + tid] + sm[P2_OFF + 512 + tid];
        __syncthreads();

        // ---- squash over capsule dim ----
        if (tid < 64) {
            float sq = 0.f;
            #pragma unroll
            for (int k = 0; k < 8; k++) {
                float cv = sm[CS_OFF + k * 64 + tid];
                sq += cv * cv;
            }
            sm[SCALE_OFF + tid] = (sq / (1.0f + sq)) * rsqrtf(sq + 1e-9f);
        }
        __syncthreads();

        if (LAST) {
            if (tid < 512)
                out[(size_t)b * 512 + tid] = sm[SCALE_OFF + (tid & 63)] * sm[CS_OFF + tid];
        } else {
            if (tid < 512) {
                float hv = sm[SCALE_OFF + (tid & 63)] * sm[CS_OFF + tid];
                sm[CS_OFF + tid] = hv;            // high, in place
            }
            __syncthreads();

            // ---- hs[k][i] = sum_o high[k][o]*S[i][o], o-halves -> hs^T[i][k] ----
            {
                int k = tid >> 7, idx = tid & 127;
                int i = idx & 63, oh = idx >> 6;
                float h = 0.f;
                #pragma unroll
                for (int oo = 0; oo < 32; oo++) {
                    int o = oh * 32 + oo;
                    h += sm[CS_OFF + k * 64 + o] * sm[SS_OFF + i * SSS + o];
                }
                sm[P2_OFF + oh * 512 + i * 8 + k] = h;
            }
            __syncthreads();
            if (tid < 512) sm[HST_OFF + tid] = sm[P2_OFF + tid] + sm[P2_OFF + 512 + tid];
            __syncthreads();

            // ---- pass 2 (warp-owned rows): delta[k][l] = sum_i hs[k][i]*X[l][i] ----
            {
                int row = row0 + (lane >> 1);      // warp w's rows
                int ks  = lane & 1;                // capsules [4ks, 4ks+4)
                unsigned long long dacc2[2] = {0ull, 0ull};
                #pragma unroll
                for (int q = 0; q < 16; q++) {
                    float4 x = *(const float4*)&sm[XS_OFF + row * XSS + q * 4];
                    #pragma unroll
                    for (int r = 0; r < 4; r++) {
                        float xvf = (r == 0) ? x.x : (r == 1) ? x.y : (r == 2) ? x.z : x.w;
                        unsigned long long xx = pack2(xvf);
                        ulonglong2 hA =
                            *(const ulonglong2*)&sm[HST_OFF + (q * 4 + r) * 8 + 4 * ks];
                        fma2(dacc2[0], xx, hA.x);
                        fma2(dacc2[1], xx, hA.y);
                    }
                }
                // own rows now dead -> prefetch next batch while stores drain
                if (bn < BATCH) issue_rows(X, bn, xs_base, row0, lane);

                float* sc = &g_scratch[(size_t)b * 4096 + row];
                unsigned int u0, u1, u2, u3;
                asm("mov.b64 {%0, %1}, %2;" : "=r"(u0), "=r"(u1) : "l"(dacc2[0]));
                asm("mov.b64 {%0, %1}, %2;" : "=r"(u2), "=r"(u3) : "l"(dacc2[1]));
                sc[(4 * ks + 0) * 512] = __uint_as_float(u0);
                sc[(4 * ks + 1) * 512] = __uint_as_float(u1);
                sc[(4 * ks + 2) * 512] = __uint_as_float(u2);
                sc[(4 * ks + 3) * 512] = __uint_as_float(u3);
            }
        }

        // next batch's softmax (W^T reads for batch b finished at pass1; all
        // later stages only touch CPART/CP/P2/CS/HST/XS)
        if (bn < BATCH) do_softmax(sm, seqlen, bn, w, lane);
        __syncthreads();   // gates W^T + XS reuse for next loop iteration
    }
}

// Deterministic 2-stage cross-batch reduction of deltas into g_B
__global__ void reduce1_kernel() {
    int j = blockIdx.x * 256 + threadIdx.x;      // 0..4095
    int base = blockIdx.y * 16;
    float s = 0.f;
    #pragma unroll
    for (int i = 0; i < 16; i++) s += g_scratch[(size_t)(base + i) * 4096 + j];
    g_part[(size_t)blockIdx.y * 4096 + j] = s;
}
__global__ void reduce2_kernel() {
    int j = blockIdx.x * 256 + threadIdx.x;
    float s = 0.f;
    #pragma unroll
    for (int i = 0; i < 64; i++) s += g_part[(size_t)i * 4096 + j];
    g_B[j] += s;
}

extern "C" void kernel_launch(void* const* d_in, const int* in_sizes, int n_in,
                              void* d_out, int out_size)
{
    const float* X     = (const float*)d_in[0];  // low_capsule [1024,512,64]
    const float* Binit = (const float*)d_in[1];  // B_init [1,8,512]
    const float* S     = (const float*)d_in[2];  // S [64,64]
    const int*   seq   = (const int*)d_in[3];    // seq_len [1024,1]
    float* out = (float*)d_out;

    cudaFuncSetAttribute(route_kernel<0>, cudaFuncAttributeMaxDynamicSharedMemorySize, SMEM_BYTES);
    cudaFuncSetAttribute(route_kernel<1>, cudaFuncAttributeMaxDynamicSharedMemorySize, SMEM_BYTES);

    void* bptr = nullptr;
    cudaGetSymbolAddress(&bptr, g_B);
    cudaMemcpyAsync(bptr, Binit, KCAP * LSEQ * sizeof(float),
                    cudaMemcpyDeviceToDevice, 0);

    // iter 0
    route_kernel<0><<<GRID, NTHREADS, SMEM_BYTES>>>(X, S, seq, out);
    reduce1_kernel<<<dim3(16, 64), 256>>>();
    reduce2_kernel<<<16, 256>>>();
    // iter 1
    route_kernel<0><<<GRID, NTHREADS, SMEM_BYTES>>>(X, S, seq, out);
    reduce1_kernel<<<dim3(16, 64), 256>>>();
    reduce2_kernel<<<16, 256>>>();
    // iter 2 (final): writes high
    route_kernel<1><<<GRID, NTHREADS, SMEM_BYTES>>>(X, S, seq, out);
}

// round 8
// speedup vs baseline: 1.3838x; 1.1458x over previous
#include <cuda_runtime.h>
#include <cstdint>
#include <cstddef>

#define BATCH 1024
#define LSEQ  512
#define DIM   64
#define KCAP  8
#define NEGV  (-65535.0f)
#define NTHREADS 1024
#define GRID  148

// ---- shared memory layout (float offsets) ----
#define WT0_OFF   0          // W^T buf0 [512][8]      4096
#define WT1_OFF   4096       // W^T buf1 [512][8]      4096
#define XS_OFF    8192       // X [512][64], 16B-chunk swizzled (chunk ^= row&15)
#define SS_OFF    40960      // S [64][67]             4288
#define CPART_OFF 45248      // pass1 partials [16][64][10]  10240
#define CP_OFF    55488      // C' [8][64]             512
#define CS_OFF    56000      // Cs/high [8][65]        520
#define SCALE_OFF 56520      // squash scale [64]      64
#define HST_OFF   56584      // hs^T [64][8]           512
#define SMEM_FLOATS 57096
#define SMEM_BYTES  (SMEM_FLOATS * 4)   // 228384 B (<= 232448 opt-in)

#define CPS 10

__device__ float g_B[KCAP * LSEQ];
__device__ float g_scratch[BATCH * KCAP * LSEQ];   // per-batch deltas (16MB)
__device__ float g_part[64 * KCAP * LSEQ];         // stage-1 reduction partials

__device__ __forceinline__ void cp_async16(uint32_t sa, const void* ga) {
    asm volatile("cp.async.cg.shared.global [%0], [%1], 16;" :: "r"(sa), "l"(ga));
}
__device__ __forceinline__ void cp_commit() {
    asm volatile("cp.async.commit_group;" ::: "memory");
}
template<int N>
__device__ __forceinline__ void cp_wait() {
    asm volatile("cp.async.wait_group %0;" :: "n"(N) : "memory");
}
__device__ __forceinline__ void bar_epi() {   // named barrier: warps 8..23 (512 thr)
    asm volatile("bar.sync 1, 512;" ::: "memory");
}
__device__ __forceinline__ unsigned long long pack2(float v) {
    unsigned long long r;
    asm("mov.b64 %0, {%1, %1};" : "=l"(r) : "r"(__float_as_uint(v)));
    return r;
}
__device__ __forceinline__ void fma2(unsigned long long& acc,
                                     unsigned long long a, unsigned long long b) {
    asm("fma.rn.f32x2 %0, %1, %2, %0;" : "+l"(acc) : "l"(a), "l"(b));
}
__device__ __forceinline__ unsigned long long add2(unsigned long long a,
                                                   unsigned long long b) {
    unsigned long long r;
    asm("add.rn.f32x2 %0, %1, %2;" : "=l"(r) : "l"(a), "l"(b));
    return r;
}

// Issue this warp's 16 X rows (2 commit groups of 8 rows), swizzled store.
__device__ __forceinline__ void issue_rows(const float* __restrict__ X, int b,
                                           uint32_t xs_base, int row0, int lane) {
    const float* Xg = X + (size_t)b * (LSEQ * DIM);
    #pragma unroll
    for (int g2 = 0; g2 < 2; g2++) {
        #pragma unroll
        for (int h = 0; h < 4; h++) {
            int s   = lane + 32 * h;               // 0..127
            int r8  = s >> 4;
            int col = s & 15;                      // 16B data chunk
            int row = row0 + 8 * g2 + r8;
            int sw  = col ^ (row & 15);            // swizzled chunk
            cp_async16(xs_base + (uint32_t)(row * 256 + sw * 16),
                       (const void*)(Xg + row * DIM + col * 4));
        }
        cp_commit();
    }
}

// Masked softmax for batch b into wt (called by warps 0..7 only; k = warp id).
__device__ __forceinline__ void do_softmax(float* __restrict__ wt,
                                           const int* __restrict__ seqlen,
                                           int b, int k, int lane) {
    const int slen = seqlen[b];
    float v[16];
    #pragma unroll
    for (int j = 0; j < 16; j++) {
        int l = lane + 32 * j;
        float bv = g_B[k * LSEQ + l];
        v[j] = (l < slen) ? bv : NEGV;
    }
    float m = v[0];
    #pragma unroll
    for (int j = 1; j < 16; j++) m = fmaxf(m, v[j]);
    #pragma unroll
    for (int off = 16; off > 0; off >>= 1)
        m = fmaxf(m, __shfl_xor_sync(0xffffffffu, m, off));
    float s = 0.f;
    #pragma unroll
    for (int j = 0; j < 16; j++) { v[j] = __expf(v[j] - m); s += v[j]; }
    #pragma unroll
    for (int off = 16; off > 0; off >>= 1)
        s += __shfl_xor_sync(0xffffffffu, s, off);
    float inv = 1.0f / s;
    #pragma unroll
    for (int j = 0; j < 16; j++)
        wt[(lane + 32 * j) * 8 + k] = v[j] * inv;   // W^T[l][k]
}

// Persistent kernel: one routing iteration. Per batch:
// pass1 -> CPART reduce -> CP -> {softmax(n+1) || Cs/squash/high/hs} -> pass2
// -> prefetch(n+1) -> (no barrier) -> pass1(n+1).   X rows fully warp-private.
template<int LAST>
__global__ void __launch_bounds__(NTHREADS, 1)
route_kernel(const float* __restrict__ X, const float* __restrict__ Sg,
             const int* __restrict__ seqlen, float* __restrict__ out)
{
    extern __shared__ float sm[];
    const int tid  = threadIdx.x;
    const int w    = tid >> 5;            // 32 warps
    const int lane = tid & 31;
    const uint32_t xs_base = (uint32_t)__cvta_generic_to_shared(&sm[XS_OFF]);
    const int row0 = w * 16;              // this warp's X rows [row0, row0+16)

    int b = blockIdx.x;

    // prologue
    issue_rows(X, b, xs_base, row0, lane);
    {
        int j = tid;                      // 1024 float4s = S [64][64]
        int d = j >> 4, o4 = (j & 15) * 4;
        float4 v = *(const float4*)(Sg + j * 4);
        float* p = &sm[SS_OFF + d * 67 + o4];
        p[0] = v.x; p[1] = v.y; p[2] = v.z; p[3] = v.w;
    }
    if (w < 8) do_softmax(&sm[WT0_OFF], seqlen, b, w, lane);
    __syncthreads();

    int par = 0;
    for (; b < BATCH; b += GRID, par ^= 1) {
        const int bn = b + GRID;
        const float* wt  = &sm[par ? WT1_OFF : WT0_OFF];
        float*       wtn = &sm[par ? WT0_OFF : WT1_OFF];

        // ---- pass 1: C'[k][d] = sum_l W[k][l]*X[l][d]; warp-private rows ----
        unsigned long long acc2[8];
        #pragma unroll
        for (int i = 0; i < 8; i++) acc2[i] = 0ull;

        #pragma unroll
        for (int g2 = 0; g2 < 2; g2++) {
            if (g2 == 0) cp_wait<1>(); else cp_wait<0>();
            __syncwarp();
            #pragma unroll
            for (int r = 0; r < 8; r++) {
                int row = row0 + 8 * g2 + r;
                int rsw = row & 15;
                float2 xv = *(const float2*)&sm[XS_OFF + row * 64 +
                                                (((lane >> 1) ^ rsw) << 2) + (lane & 1) * 2];
                ulonglong2 wA = *(const ulonglong2*)&wt[row * 8];
                ulonglong2 wB = *(const ulonglong2*)&wt[row * 8 + 4];
                unsigned long long xx0 = pack2(xv.x);
                unsigned long long xx1 = pack2(xv.y);
                fma2(acc2[0], xx0, wA.x); fma2(acc2[1], xx0, wA.y);
                fma2(acc2[2], xx0, wB.x); fma2(acc2[3], xx0, wB.y);
                fma2(acc2[4], xx1, wA.x); fma2(acc2[5], xx1, wA.y);
                fma2(acc2[6], xx1, wB.x); fma2(acc2[7], xx1, wB.y);
            }
        }

        // LAST: X dead after pass1 -> prefetch own rows now (warp-private, no hazard)
        if (LAST && bn < BATCH) issue_rows(X, bn, xs_base, row0, lane);

        // ---- two-wave cross-warp reduction into CPART [16][64][10] ----
        if (w < 16) {
            #pragma unroll
            for (int dd = 0; dd < 2; dd++)
                #pragma unroll
                for (int kp = 0; kp < 4; kp++) {
                    int d = 2 * lane + dd;
                    *(unsigned long long*)&sm[CPART_OFF + w * 640 + d * CPS + 2 * kp]
                        = acc2[dd * 4 + kp];
                }
        }
        __syncthreads();
        if (w >= 16) {
            int p = w - 16;
            #pragma unroll
            for (int dd = 0; dd < 2; dd++)
                #pragma unroll
                for (int kp = 0; kp < 4; kp++) {
                    int d = 2 * lane + dd;
                    unsigned long long* ptr =
                        (unsigned long long*)&sm[CPART_OFF + p * 640 + d * CPS + 2 * kp];
                    *ptr = add2(*ptr, acc2[dd * 4 + kp]);
                }
        }
        __syncthreads();
        if (tid < 512) {
            int k = tid >> 6, d = tid & 63;
            float s = 0.f;
            #pragma unroll
            for (int p = 0; p < 16; p++) s += sm[CPART_OFF + p * 640 + d * CPS + k];
            sm[CP_OFF + k * 64 + d] = s;
        }
        __syncthreads();

        // ---- step 4: softmax(n+1) on warps 0-7 || epilogue on warps 8-23 ----
        if (w < 8) {
            if (bn < BATCH) do_softmax(wtn, seqlen, bn, w, lane);
        } else if (w < 24) {
            const int t = tid - 256;          // 0..511
            const int k = t >> 6, o = t & 63; // warp spans one k

            // Cs[k][o] = sum_d C'[k][d]*S[d][o]
            float a = 0.f;
            #pragma unroll
            for (int d = 0; d < 64; d++)
                a += sm[CP_OFF + k * 64 + d] * sm[SS_OFF + d * 67 + o];
            sm[CS_OFF + k * 65 + o] = a;
            bar_epi();

            if (t < 64) {                     // squash scale (2 warps)
                float sq = 0.f;
                #pragma unroll
                for (int k8 = 0; k8 < 8; k8++) {
                    float cv = sm[CS_OFF + k8 * 65 + t];
                    sq += cv * cv;
                }
                sm[SCALE_OFF + t] = (sq / (1.0f + sq)) * rsqrtf(sq + 1e-9f);
            }
            bar_epi();

            float hv = sm[SCALE_OFF + o] * sm[CS_OFF + k * 65 + o];
            if (LAST) {
                out[(size_t)b * 512 + t] = hv;            // t == k*64+o
            } else {
                sm[CS_OFF + k * 65 + o] = hv;             // high, in place
                bar_epi();
                // hs[k][i] = sum_o high[k][o]*S[i][o]  -> hs^T[i][k]
                const int i = o;
                float h = 0.f;
                #pragma unroll
                for (int oo = 0; oo < 64; oo++)
                    h += sm[CS_OFF + k * 65 + oo] * sm[SS_OFF + i * 67 + oo];
                sm[HST_OFF + i * 8 + k] = h;
            }
        }
        __syncthreads();   // joins soft/epi/idle; publishes wtn + HST

        if (!LAST) {
            // ---- pass 2 (own rows): delta[k][l] = sum_i hs[k][i]*X[l][i] ----
            const int row = row0 + (lane >> 1);
            const int ks  = lane & 1;          // capsules [4ks, 4ks+4)
            const int rsw = row & 15;
            unsigned long long dacc2[2] = {0ull, 0ull};
            #pragma unroll
            for (int q = 0; q < 16; q++) {
                float4 x = *(const float4*)&sm[XS_OFF + row * 64 + ((q ^ rsw) << 2)];
                #pragma unroll
                for (int r = 0; r < 4; r++) {
                    float xvf = (r == 0) ? x.x : (r == 1) ? x.y : (r == 2) ? x.z : x.w;
                    unsigned long long xx = pack2(xvf);
                    ulonglong2 hA =
                        *(const ulonglong2*)&sm[HST_OFF + (q * 4 + r) * 8 + 4 * ks];
                    fma2(dacc2[0], xx, hA.x);
                    fma2(dacc2[1], xx, hA.y);
                }
            }
            // own rows dead -> prefetch next batch (no barrier to next pass1)
            if (bn < BATCH) issue_rows(X, bn, xs_base, row0, lane);

            float* sc = &g_scratch[(size_t)b * 4096 + row];
            unsigned int u0, u1, u2, u3;
            asm("mov.b64 {%0, %1}, %2;" : "=r"(u0), "=r"(u1) : "l"(dacc2[0]));
            asm("mov.b64 {%0, %1}, %2;" : "=r"(u2), "=r"(u3) : "l"(dacc2[1]));
            sc[(4 * ks + 0) * 512] = __uint_as_float(u0);
            sc[(4 * ks + 1) * 512] = __uint_as_float(u1);
            sc[(4 * ks + 2) * 512] = __uint_as_float(u2);
            sc[(4 * ks + 3) * 512] = __uint_as_float(u3);
        }
        // no trailing barrier: next pass1 gated by per-warp cp_wait; wtn/CPART
        // hazards are covered by the step-4 barrier and the CPART barriers.
    }
}

// Deterministic 2-stage cross-batch reduction of deltas into g_B
__global__ void reduce1_kernel() {
    int j = blockIdx.x * 256 + threadIdx.x;      // 0..4095
    int base = blockIdx.y * 16;
    float s = 0.f;
    #pragma unroll
    for (int i = 0; i < 16; i++) s += g_scratch[(size_t)(base + i) * 4096 + j];
    g_part[(size_t)blockIdx.y * 4096 + j] = s;
}
__global__ void reduce2_kernel() {
    int j = blockIdx.x * 256 + threadIdx.x;
    float s = 0.f;
    #pragma unroll
    for (int i = 0; i < 64; i++) s += g_part[(size_t)i * 4096 + j];
    g_B[j] += s;
}

extern "C" void kernel_launch(void* const* d_in, const int* in_sizes, int n_in,
                              void* d_out, int out_size)
{
    const float* X     = (const float*)d_in[0];  // low_capsule [1024,512,64]
    const float* Binit = (const float*)d_in[1];  // B_init [1,8,512]
    const float* S     = (const float*)d_in[2];  // S [64,64]
    const int*   seq   = (const int*)d_in[3];    // seq_len [1024,1]
    float* out = (float*)d_out;

    cudaFuncSetAttribute(route_kernel<0>, cudaFuncAttributeMaxDynamicSharedMemorySize, SMEM_BYTES);
    cudaFuncSetAttribute(route_kernel<1>, cudaFuncAttributeMaxDynamicSharedMemorySize, SMEM_BYTES);

    void* bptr = nullptr;
    cudaGetSymbolAddress(&bptr, g_B);
    cudaMemcpyAsync(bptr, Binit, KCAP * LSEQ * sizeof(float),
                    cudaMemcpyDeviceToDevice, 0);

    // iter 0
    route_kernel<0><<<GRID, NTHREADS, SMEM_BYTES>>>(X, S, seq, out);
    reduce1_kernel<<<dim3(16, 64), 256>>>();
    reduce2_kernel<<<16, 256>>>();
    // iter 1
    route_kernel<0><<<GRID, NTHREADS, SMEM_BYTES>>>(X, S, seq, out);
    reduce1_kernel<<<dim3(16, 64), 256>>>();
    reduce2_kernel<<<16, 256>>>();
    // iter 2 (final): writes high
    route_kernel<1><<<GRID, NTHREADS, SMEM_BYTES>>>(X, S, seq, out);
}